// round 15
// baseline (speedup 1.0000x reference)
#include <cuda_runtime.h>
#include <cuda_fp16.h>
#include <cstdint>
#include <math.h>

#define BATCH 8
#define SEQ   2048
#define DIM   1024
#define H3    3072

// Scratch (__device__ globals; no allocs allowed)
__device__ __half g_Xh [(size_t)BATCH * SEQ * DIM];   // x in fp16
__device__ __half g_W3 [(size_t)H3 * DIM];            // [Wq;Wk;Wv]^T packed, K-major [3H][D]
__device__ float  g_b3 [H3];                          // packed bias
__device__ __half g_QKV[(size_t)BATCH * SEQ * H3];    // [s][3H] fp16 (V third unused)
__device__ __half g_Vt [(size_t)BATCH * DIM * SEQ];   // V^T per batch [H][S] fp16
__device__ float  g_S  [(size_t)BATCH * SEQ * SEQ];   // scores fp32
__device__ __half g_P  [(size_t)BATCH * SEQ * SEQ];   // softmax probs fp16

// ------------------------------ helpers ------------------------------
__device__ __forceinline__ uint32_t smem_u32(const void* p) {
    uint32_t a;
    asm("{ .reg .u64 t; cvta.to.shared.u64 t, %1; cvt.u32.u64 %0, t; }"
        : "=r"(a) : "l"(p));
    return a;
}

#define LDSM_X4(r, addr) \
    asm volatile("ldmatrix.sync.aligned.m8n8.x4.shared.b16 {%0,%1,%2,%3}, [%4];" \
        : "=r"((r)[0]), "=r"((r)[1]), "=r"((r)[2]), "=r"((r)[3]) : "r"(addr))

#define MMA16816(c, a, b0_, b1_) \
    asm volatile("mma.sync.aligned.m16n8k16.row.col.f32.f16.f16.f32 " \
        "{%0,%1,%2,%3}, {%4,%5,%6,%7}, {%8,%9}, {%0,%1,%2,%3};" \
        : "+f"((c)[0]), "+f"((c)[1]), "+f"((c)[2]), "+f"((c)[3]) \
        : "r"((a)[0]), "r"((a)[1]), "r"((a)[2]), "r"((a)[3]), \
          "r"(b0_), "r"(b1_))

#define CP_ASYNC16(dst, src) \
    asm volatile("cp.async.cg.shared.global [%0], [%1], 16;" :: "r"(dst), "l"(src))

#define NST     4
#define ROWPAD  80                        // 32 halves (64B) padded to 80B
#define ASTAGE  (128 * ROWPAD)            // 10240B
#define STAGE   (2 * ASTAGE)              // A + B = 20480B
#define SMEM_BYTES (NST * STAGE)          // 81920B

// ---------------------------------------------------------------------------
// fp16 tensor-core GEMM: C[m0:+128, n0:+128] = A * B^T  (K-major operands)
//   A [M,K] row-major fp16 (ld = lda), B [N,K] row-major fp16 (ld = ldb)
// MODE 0: QKV. n0<2048: C half += bias.  n0>=2048: V-third -> bias + transposed
//         store into Vt[b][h][s] via smem (fuses the V transpose kernel).
// MODE 1: C float, *= alpha, batched.
// 128 threads, 4 warps in 2x2; warp tile 64x64 (32 indep MMAs per k16).
// R9 structure: NST=4, BK=32, interleaved LDSM/MMA, 2 CTAs/SM.
// ---------------------------------------------------------------------------
template <int MODE>
__global__ __launch_bounds__(128, 2) void hgemm(
    const __half* __restrict__ Ag, const __half* __restrict__ Bg,
    const float* __restrict__ bias, void* __restrict__ Cv,
    __half* __restrict__ VtG,
    int lda, int ldb, int ldc, int kIters,
    long sA, long sB, long sC, float alpha)
{
    extern __shared__ char dsm[];
    const uint32_t sm0 = smem_u32(dsm);
    const int tid = threadIdx.x;
    const int wid = tid >> 5, lane = tid & 31;
    const __half* A = Ag + (long)blockIdx.z * sA;
    const __half* B = Bg + (long)blockIdx.z * sB;
    const long m0 = (long)blockIdx.y * 128;
    const long n0 = (long)blockIdx.x * 128;
    const int mw = (wid >> 1) * 64;   // warp row offset in tile
    const int nw = (wid & 1) * 64;    // warp col offset in tile

    const int g = lane >> 2, tig = lane & 3;
    // ldmatrix per-lane address offsets (bytes), conflict-free with ROWPAD=80
    const uint32_t aOff = ((lane & 7) + ((lane >> 3) & 1) * 8) * ROWPAD
                        + ((lane >> 4) & 1) * 16;
    const uint32_t bOff = ((lane & 7) + ((lane >> 4) & 1) * 8) * ROWPAD
                        + ((lane >> 3) & 1) * 16;

    auto load_stage = [&](int s, int it) {
        const uint32_t ab = sm0 + s * STAGE;
        const long kb = (long)it * 32;
        #pragma unroll
        for (int i = 0; i < 4; ++i) {                 // A: 128 rows x 64B
            int idx = tid + i * 128;
            int row = idx >> 2, c = idx & 3;
            const __half* src = A + (m0 + row) * (long)lda + kb + c * 8;
            CP_ASYNC16(ab + row * ROWPAD + c * 16, src);
        }
        #pragma unroll
        for (int i = 0; i < 4; ++i) {                 // B: 128 rows x 64B
            int idx = tid + i * 128;
            int row = idx >> 2, c = idx & 3;
            const __half* src = B + (n0 + row) * (long)ldb + kb + c * 8;
            CP_ASYNC16(ab + ASTAGE + row * ROWPAD + c * 16, src);
        }
    };

    float acc[32][4];
    #pragma unroll
    for (int t = 0; t < 32; ++t)
        acc[t][0] = acc[t][1] = acc[t][2] = acc[t][3] = 0.f;

    #pragma unroll
    for (int s = 0; s < NST - 1; ++s) {
        load_stage(s, s);
        asm volatile("cp.async.commit_group;" ::: "memory");
    }

    for (int it = 0; it < kIters; ++it) {
        asm volatile("cp.async.wait_group 2;" ::: "memory");
        __syncthreads();

        {   // prefetch next stage (writes stage computed 3 iters ago — safe)
            int nit = it + NST - 1;
            if (nit < kIters) load_stage(nit & (NST - 1), nit);
            asm volatile("cp.async.commit_group;" ::: "memory");
        }

        const uint32_t ab = sm0 + (it & (NST - 1)) * STAGE;
        const uint32_t bb = ab + ASTAGE;
        const uint32_t aBase = ab + mw * ROWPAD + aOff;
        const uint32_t bBase = bb + nw * ROWPAD + bOff;

        uint32_t af0[4][4], bf0[4][4], af1[4][4], bf1[4][4];

        // kk=0 fragment loads
        #pragma unroll
        for (int mi = 0; mi < 4; ++mi)
            LDSM_X4(af0[mi], aBase + mi * (16 * ROWPAD));
        #pragma unroll
        for (int nj = 0; nj < 4; ++nj)
            LDSM_X4(bf0[nj], bBase + nj * (16 * ROWPAD));

        // kk=0 MMAs, first half (mi 0..1)
        #pragma unroll
        for (int mi = 0; mi < 2; ++mi)
            #pragma unroll
            for (int ni = 0; ni < 8; ++ni)
                MMA16816(acc[mi * 8 + ni], af0[mi],
                         bf0[ni >> 1][(ni & 1) * 2],
                         bf0[ni >> 1][(ni & 1) * 2 + 1]);

        // kk=1 A fragments — hidden under kk0 MMA stream
        #pragma unroll
        for (int mi = 0; mi < 4; ++mi)
            LDSM_X4(af1[mi], aBase + mi * (16 * ROWPAD) + 32);

        // kk=0 MMAs, second half (mi 2..3); af0 dies here
        #pragma unroll
        for (int mi = 2; mi < 4; ++mi)
            #pragma unroll
            for (int ni = 0; ni < 8; ++ni)
                MMA16816(acc[mi * 8 + ni], af0[mi],
                         bf0[ni >> 1][(ni & 1) * 2],
                         bf0[ni >> 1][(ni & 1) * 2 + 1]);

        // kk=1 B fragments
        #pragma unroll
        for (int nj = 0; nj < 4; ++nj)
            LDSM_X4(bf1[nj], bBase + nj * (16 * ROWPAD) + 32);

        // kk=1 MMAs
        #pragma unroll
        for (int mi = 0; mi < 4; ++mi)
            #pragma unroll
            for (int ni = 0; ni < 8; ++ni)
                MMA16816(acc[mi * 8 + ni], af1[mi],
                         bf1[ni >> 1][(ni & 1) * 2],
                         bf1[ni >> 1][(ni & 1) * 2 + 1]);
    }

    // ---- epilogue ----
    if (MODE == 0) {
        if (n0 < 2048) {
            // Q/K thirds: straight biased store to QKV
            __half* C = (__half*)Cv;
            #pragma unroll
            for (int mi = 0; mi < 4; ++mi) {
                long r0 = m0 + mw + mi * 16 + g;
                #pragma unroll
                for (int ni = 0; ni < 8; ++ni) {
                    long col = n0 + nw + ni * 8 + 2 * tig;
                    float bx = __ldg(&bias[col]), by = __ldg(&bias[col + 1]);
                    const float* a = acc[mi * 8 + ni];
                    *(__half2*)(C + r0 * (long)ldc + col) =
                        __floats2half2_rn(a[0] + bx, a[1] + by);
                    *(__half2*)(C + (r0 + 8) * (long)ldc + col) =
                        __floats2half2_rn(a[2] + bx, a[3] + by);
                }
            }
        } else {
            // V third: bias, round-trip through smem, store transposed to Vt.
            __syncthreads();   // all warps done with stage smem (acc in regs)
            __half2* sm2 = (__half2*)dsm;   // [s 0..127][65 half2 words]
            #pragma unroll
            for (int mi = 0; mi < 4; ++mi) {
                int r0 = mw + mi * 16 + g;
                #pragma unroll
                for (int ni = 0; ni < 8; ++ni) {
                    int c = nw + ni * 8 + 2 * tig;
                    long col = n0 + c;
                    float bx = __ldg(&bias[col]), by = __ldg(&bias[col + 1]);
                    const float* a = acc[mi * 8 + ni];
                    sm2[r0 * 65 + (c >> 1)]       = __floats2half2_rn(a[0] + bx, a[1] + by);
                    sm2[(r0 + 8) * 65 + (c >> 1)] = __floats2half2_rn(a[2] + bx, a[3] + by);
                }
            }
            __syncthreads();
            const long b     = m0 >> 11;        // batch (m0 / 2048)
            const long sBase = (m0 & 2047);     // s offset within batch
            __half* VtB = VtG + b * (long)DIM * SEQ;
            #pragma unroll 1
            for (int hh = 0; hh < 32; ++hh) {
                int h = wid * 32 + hh;          // 0..127 within tile
                long hg = (n0 - 2048) + h;      // global head-dim row
                __half tmp[4];
                #pragma unroll
                for (int j = 0; j < 4; ++j) {
                    int s = lane * 4 + j;
                    __half2 w2 = sm2[s * 65 + (h >> 1)];
                    tmp[j] = (h & 1) ? __high2half(w2) : __low2half(w2);
                }
                *(uint2*)(VtB + hg * SEQ + sBase + lane * 4) = *(uint2*)tmp;
            }
        }
    } else {
        float* C = (float*)Cv + (long)blockIdx.z * sC;
        #pragma unroll
        for (int mi = 0; mi < 4; ++mi) {
            long r0 = m0 + mw + mi * 16 + g;
            #pragma unroll
            for (int ni = 0; ni < 8; ++ni) {
                long col = n0 + nw + ni * 8 + 2 * tig;
                const float* a = acc[mi * 8 + ni];
                float2 lo; lo.x = a[0] * alpha; lo.y = a[1] * alpha;
                float2 hi; hi.x = a[2] * alpha; hi.y = a[3] * alpha;
                *(float2*)(C + r0 * (long)ldc + col) = lo;
                *(float2*)(C + (r0 + 8) * (long)ldc + col) = hi;
            }
        }
    }
}

// ---------------------------------------------------------------------------
// fp32 -> fp16 copy
// ---------------------------------------------------------------------------
__global__ void f2h(const float* __restrict__ in, __half* __restrict__ out, long n)
{
    for (long i = ((long)blockIdx.x * 256 + threadIdx.x) * 4; i < n;
         i += (long)gridDim.x * 256 * 4) {
        float4 v = *reinterpret_cast<const float4*>(in + i);
        *(__half2*)(out + i)     = __floats2half2_rn(v.x, v.y);
        *(__half2*)(out + i + 2) = __floats2half2_rn(v.z, v.w);
    }
}

// ---------------------------------------------------------------------------
// Weight pack: W3[(z*1024 + h)][d] = (half)W_z[d][h]   (transpose + convert)
// ---------------------------------------------------------------------------
__global__ void wconv(const float* __restrict__ Wq, const float* __restrict__ Wk,
                      const float* __restrict__ Wv, __half* __restrict__ W3)
{
    __shared__ float t[32][33];
    const float* W = blockIdx.z == 0 ? Wq : (blockIdx.z == 1 ? Wk : Wv);
    const int d0 = blockIdx.y * 32, h0 = blockIdx.x * 32;
    const int tx = threadIdx.x, ty = threadIdx.y;
    #pragma unroll
    for (int i = 0; i < 32; i += 8)
        t[ty + i][tx] = W[(long)(d0 + ty + i) * DIM + h0 + tx];
    __syncthreads();
    #pragma unroll
    for (int i = 0; i < 32; i += 8)
        W3[((size_t)blockIdx.z * DIM + h0 + ty + i) * DIM + d0 + tx] =
            __float2half_rn(t[tx][ty + i]);
}

__global__ void packb(const float* __restrict__ bq, const float* __restrict__ bk,
                      const float* __restrict__ bv, float* __restrict__ b3)
{
    int i = blockIdx.x * 256 + threadIdx.x;
    if (i < H3)
        b3[i] = i < DIM ? bq[i] : (i < 2 * DIM ? bk[i - DIM] : bv[i - 2 * DIM]);
}

// ---------------------------------------------------------------------------
// Row softmax over SEQ=2048: S (fp32) -> P (fp16). Warp-shuffle reductions.
// ---------------------------------------------------------------------------
__global__ __launch_bounds__(256) void softmax_rows(const float* __restrict__ S,
                                                    __half* __restrict__ P)
{
    const float* p = S + (long)blockIdx.x * SEQ;
    __half* q = P + (long)blockIdx.x * SEQ;
    const int tid = threadIdx.x;
    const int wid = tid >> 5, lane = tid & 31;
    __shared__ float red[8];

    float4 v0 = *(const float4*)(p + tid * 4);
    float4 v1 = *(const float4*)(p + 1024 + tid * 4);

    float m = fmaxf(fmaxf(fmaxf(v0.x, v0.y), fmaxf(v0.z, v0.w)),
                    fmaxf(fmaxf(v1.x, v1.y), fmaxf(v1.z, v1.w)));
    #pragma unroll
    for (int s = 16; s > 0; s >>= 1)
        m = fmaxf(m, __shfl_xor_sync(0xFFFFFFFFu, m, s));
    if (lane == 0) red[wid] = m;
    __syncthreads();
    float m0 = red[0];
    #pragma unroll
    for (int w = 1; w < 8; ++w) m0 = fmaxf(m0, red[w]);
    __syncthreads();

    v0.x = __expf(v0.x - m0); v0.y = __expf(v0.y - m0);
    v0.z = __expf(v0.z - m0); v0.w = __expf(v0.w - m0);
    v1.x = __expf(v1.x - m0); v1.y = __expf(v1.y - m0);
    v1.z = __expf(v1.z - m0); v1.w = __expf(v1.w - m0);

    float sum = (v0.x + v0.y) + (v0.z + v0.w) + (v1.x + v1.y) + (v1.z + v1.w);
    #pragma unroll
    for (int s = 16; s > 0; s >>= 1)
        sum += __shfl_xor_sync(0xFFFFFFFFu, sum, s);
    if (lane == 0) red[wid] = sum;
    __syncthreads();
    float tot = red[0];
    #pragma unroll
    for (int w = 1; w < 8; ++w) tot += red[w];
    const float inv = 1.f / tot;

    *(__half2*)(q + tid * 4)     = __floats2half2_rn(v0.x * inv, v0.y * inv);
    *(__half2*)(q + tid * 4 + 2) = __floats2half2_rn(v0.z * inv, v0.w * inv);
    *(__half2*)(q + 1024 + tid * 4)     = __floats2half2_rn(v1.x * inv, v1.y * inv);
    *(__half2*)(q + 1024 + tid * 4 + 2) = __floats2half2_rn(v1.z * inv, v1.w * inv);
}

// ---------------------------------------------------------------------------
extern "C" void kernel_launch(void* const* d_in, const int* in_sizes, int n_in,
                              void* d_out, int out_size)
{
    const float* x  = (const float*)d_in[0];
    const float* Wq = (const float*)d_in[1];
    const float* bq = (const float*)d_in[2];
    const float* Wk = (const float*)d_in[3];
    const float* bk = (const float*)d_in[4];
    const float* Wv = (const float*)d_in[5];
    const float* bv = (const float*)d_in[6];
    float* out = (float*)d_out;

    __half *Xh, *W3, *QKV, *Vt, *P;
    float *b3, *S;
    cudaGetSymbolAddress((void**)&Xh,  g_Xh);
    cudaGetSymbolAddress((void**)&W3,  g_W3);
    cudaGetSymbolAddress((void**)&b3,  g_b3);
    cudaGetSymbolAddress((void**)&QKV, g_QKV);
    cudaGetSymbolAddress((void**)&Vt,  g_Vt);
    cudaGetSymbolAddress((void**)&S,   g_S);
    cudaGetSymbolAddress((void**)&P,   g_P);

    cudaFuncSetAttribute(hgemm<0>, cudaFuncAttributeMaxDynamicSharedMemorySize, SMEM_BYTES);
    cudaFuncSetAttribute(hgemm<1>, cudaFuncAttributeMaxDynamicSharedMemorySize, SMEM_BYTES);

    const long SD = (long)SEQ * DIM;
    const long SS = (long)SEQ * SEQ;
    const long SH3 = (long)SEQ * H3;
    dim3 tb(32, 8);

    // input conversions
    f2h<<<2048, 256>>>(x, Xh, (long)BATCH * SEQ * DIM);
    wconv<<<dim3(32, 32, 3), tb>>>(Wq, Wk, Wv, W3);
    packb<<<12, 256>>>(bq, bk, bv, b3);

    // fused QKV projection (+V transpose): [16384,1024] x [3072,1024]^T + bias
    hgemm<0><<<dim3(H3 / 128, (BATCH * SEQ) / 128, 1), 128, SMEM_BYTES>>>(
        Xh, W3, b3, QKV, Vt, DIM, DIM, H3, DIM / 32, 0, 0, 0, 1.f);

    // scores = Q K^T / 32 (fp32 out)
    hgemm<1><<<dim3(SEQ / 128, SEQ / 128, BATCH), 128, SMEM_BYTES>>>(
        QKV, QKV + DIM, nullptr, S, nullptr, H3, H3, SEQ, DIM / 32,
        SH3, SH3, SS, 1.f / 32.f);

    // softmax -> fp16 probs
    softmax_rows<<<BATCH * SEQ, 256>>>(S, P);

    // out = P V (fp32 out), B operand = Vt [H][S] K-major
    hgemm<1><<<dim3(DIM / 128, SEQ / 128, BATCH), 128, SMEM_BYTES>>>(
        P, Vt, nullptr, out, nullptr, SEQ, SEQ, DIM, SEQ / 32,
        SS, SD, SD, 1.f);
}

// round 16
// speedup vs baseline: 1.0145x; 1.0145x over previous
#include <cuda_runtime.h>
#include <cuda_fp16.h>
#include <cstdint>
#include <math.h>

#define BATCH 8
#define SEQ   2048
#define DIM   1024
#define H3    3072

// Scratch (__device__ globals; no allocs allowed)
__device__ __half g_Xh [(size_t)BATCH * SEQ * DIM];   // x in fp16
__device__ __half g_W3 [(size_t)H3 * DIM];            // [Wq;Wk;Wv]^T packed, K-major [3H][D]
__device__ float  g_b3 [H3];                          // packed bias
__device__ __half g_QKV[(size_t)BATCH * SEQ * H3];    // [s][3H] fp16
__device__ __half g_Vt [(size_t)BATCH * DIM * SEQ];   // V^T per batch [H][S] fp16
__device__ __half g_S  [(size_t)BATCH * SEQ * SEQ];   // scores fp16
__device__ __half g_P  [(size_t)BATCH * SEQ * SEQ];   // softmax probs fp16

// ------------------------------ helpers ------------------------------
__device__ __forceinline__ uint32_t smem_u32(const void* p) {
    uint32_t a;
    asm("{ .reg .u64 t; cvta.to.shared.u64 t, %1; cvt.u32.u64 %0, t; }"
        : "=r"(a) : "l"(p));
    return a;
}

#define LDSM_X4(r, addr) \
    asm volatile("ldmatrix.sync.aligned.m8n8.x4.shared.b16 {%0,%1,%2,%3}, [%4];" \
        : "=r"((r)[0]), "=r"((r)[1]), "=r"((r)[2]), "=r"((r)[3]) : "r"(addr))

#define MMA16816(c, a, b0_, b1_) \
    asm volatile("mma.sync.aligned.m16n8k16.row.col.f32.f16.f16.f32 " \
        "{%0,%1,%2,%3}, {%4,%5,%6,%7}, {%8,%9}, {%0,%1,%2,%3};" \
        : "+f"((c)[0]), "+f"((c)[1]), "+f"((c)[2]), "+f"((c)[3]) \
        : "r"((a)[0]), "r"((a)[1]), "r"((a)[2]), "r"((a)[3]), \
          "r"(b0_), "r"(b1_))

#define CP_ASYNC16(dst, src) \
    asm volatile("cp.async.cg.shared.global [%0], [%1], 16;" :: "r"(dst), "l"(src))

#define NST     4
#define ROWPAD  80                        // 32 halves (64B) padded to 80B
#define ASTAGE  (128 * ROWPAD)            // 10240B
#define STAGE   (2 * ASTAGE)              // A + B = 20480B
#define SMEM_BYTES (NST * STAGE)          // 81920B

// ---------------------------------------------------------------------------
// fp16 tensor-core GEMM: C[m0:+128, n0:+128] = A * B^T  (K-major operands)
//   A [M,K] row-major fp16 (ld = lda), B [N,K] row-major fp16 (ld = ldb)
// MODE 0: C half, += bias (fp32), no batch (QKV).
// MODE 1: C float, *= alpha, batched (PV -> final out).
// MODE 2: C half,  *= alpha, batched (scores -> fp16 S).
// 128 threads, 4 warps in 2x2; warp tile 64x64 (32 indep MMAs per k16).
// R9 structure: NST=4, BK=32, interleaved LDSM/MMA, 2 CTAs/SM.
// ---------------------------------------------------------------------------
template <int MODE>
__global__ __launch_bounds__(128, 2) void hgemm(
    const __half* __restrict__ Ag, const __half* __restrict__ Bg,
    const float* __restrict__ bias, void* __restrict__ Cv,
    int lda, int ldb, int ldc, int kIters,
    long sA, long sB, long sC, float alpha)
{
    extern __shared__ char dsm[];
    const uint32_t sm0 = smem_u32(dsm);
    const int tid = threadIdx.x;
    const int wid = tid >> 5, lane = tid & 31;
    const __half* A = Ag + (long)blockIdx.z * sA;
    const __half* B = Bg + (long)blockIdx.z * sB;
    const long m0 = (long)blockIdx.y * 128;
    const long n0 = (long)blockIdx.x * 128;
    const int mw = (wid >> 1) * 64;   // warp row offset in tile
    const int nw = (wid & 1) * 64;    // warp col offset in tile

    const int g = lane >> 2, tig = lane & 3;
    // ldmatrix per-lane address offsets (bytes), conflict-free with ROWPAD=80
    const uint32_t aOff = ((lane & 7) + ((lane >> 3) & 1) * 8) * ROWPAD
                        + ((lane >> 4) & 1) * 16;
    const uint32_t bOff = ((lane & 7) + ((lane >> 4) & 1) * 8) * ROWPAD
                        + ((lane >> 3) & 1) * 16;

    auto load_stage = [&](int s, int it) {
        const uint32_t ab = sm0 + s * STAGE;
        const long kb = (long)it * 32;
        #pragma unroll
        for (int i = 0; i < 4; ++i) {                 // A: 128 rows x 64B
            int idx = tid + i * 128;
            int row = idx >> 2, c = idx & 3;
            const __half* src = A + (m0 + row) * (long)lda + kb + c * 8;
            CP_ASYNC16(ab + row * ROWPAD + c * 16, src);
        }
        #pragma unroll
        for (int i = 0; i < 4; ++i) {                 // B: 128 rows x 64B
            int idx = tid + i * 128;
            int row = idx >> 2, c = idx & 3;
            const __half* src = B + (n0 + row) * (long)ldb + kb + c * 8;
            CP_ASYNC16(ab + ASTAGE + row * ROWPAD + c * 16, src);
        }
    };

    float acc[32][4];
    #pragma unroll
    for (int t = 0; t < 32; ++t)
        acc[t][0] = acc[t][1] = acc[t][2] = acc[t][3] = 0.f;

    #pragma unroll
    for (int s = 0; s < NST - 1; ++s) {
        load_stage(s, s);
        asm volatile("cp.async.commit_group;" ::: "memory");
    }

    for (int it = 0; it < kIters; ++it) {
        asm volatile("cp.async.wait_group 2;" ::: "memory");
        __syncthreads();

        {   // prefetch next stage (writes stage computed 3 iters ago — safe)
            int nit = it + NST - 1;
            if (nit < kIters) load_stage(nit & (NST - 1), nit);
            asm volatile("cp.async.commit_group;" ::: "memory");
        }

        const uint32_t ab = sm0 + (it & (NST - 1)) * STAGE;
        const uint32_t bb = ab + ASTAGE;
        const uint32_t aBase = ab + mw * ROWPAD + aOff;
        const uint32_t bBase = bb + nw * ROWPAD + bOff;

        uint32_t af0[4][4], bf0[4][4], af1[4][4], bf1[4][4];

        // kk=0 fragment loads
        #pragma unroll
        for (int mi = 0; mi < 4; ++mi)
            LDSM_X4(af0[mi], aBase + mi * (16 * ROWPAD));
        #pragma unroll
        for (int nj = 0; nj < 4; ++nj)
            LDSM_X4(bf0[nj], bBase + nj * (16 * ROWPAD));

        // kk=0 MMAs, first half (mi 0..1)
        #pragma unroll
        for (int mi = 0; mi < 2; ++mi)
            #pragma unroll
            for (int ni = 0; ni < 8; ++ni)
                MMA16816(acc[mi * 8 + ni], af0[mi],
                         bf0[ni >> 1][(ni & 1) * 2],
                         bf0[ni >> 1][(ni & 1) * 2 + 1]);

        // kk=1 A fragments — hidden under kk0 MMA stream
        #pragma unroll
        for (int mi = 0; mi < 4; ++mi)
            LDSM_X4(af1[mi], aBase + mi * (16 * ROWPAD) + 32);

        // kk=0 MMAs, second half (mi 2..3); af0 dies here
        #pragma unroll
        for (int mi = 2; mi < 4; ++mi)
            #pragma unroll
            for (int ni = 0; ni < 8; ++ni)
                MMA16816(acc[mi * 8 + ni], af0[mi],
                         bf0[ni >> 1][(ni & 1) * 2],
                         bf0[ni >> 1][(ni & 1) * 2 + 1]);

        // kk=1 B fragments
        #pragma unroll
        for (int nj = 0; nj < 4; ++nj)
            LDSM_X4(bf1[nj], bBase + nj * (16 * ROWPAD) + 32);

        // kk=1 MMAs
        #pragma unroll
        for (int mi = 0; mi < 4; ++mi)
            #pragma unroll
            for (int ni = 0; ni < 8; ++ni)
                MMA16816(acc[mi * 8 + ni], af1[mi],
                         bf1[ni >> 1][(ni & 1) * 2],
                         bf1[ni >> 1][(ni & 1) * 2 + 1]);
    }

    // ---- epilogue: warp writes its 64x64 tile ----
    if (MODE == 0) {
        __half* C = (__half*)Cv;
        #pragma unroll
        for (int mi = 0; mi < 4; ++mi) {
            long r0 = m0 + mw + mi * 16 + g;
            #pragma unroll
            for (int ni = 0; ni < 8; ++ni) {
                long col = n0 + nw + ni * 8 + 2 * tig;
                float bx = __ldg(&bias[col]), by = __ldg(&bias[col + 1]);
                const float* a = acc[mi * 8 + ni];
                *(__half2*)(C + r0 * (long)ldc + col) =
                    __floats2half2_rn(a[0] + bx, a[1] + by);
                *(__half2*)(C + (r0 + 8) * (long)ldc + col) =
                    __floats2half2_rn(a[2] + bx, a[3] + by);
            }
        }
    } else if (MODE == 1) {
        float* C = (float*)Cv + (long)blockIdx.z * sC;
        #pragma unroll
        for (int mi = 0; mi < 4; ++mi) {
            long r0 = m0 + mw + mi * 16 + g;
            #pragma unroll
            for (int ni = 0; ni < 8; ++ni) {
                long col = n0 + nw + ni * 8 + 2 * tig;
                const float* a = acc[mi * 8 + ni];
                float2 lo; lo.x = a[0] * alpha; lo.y = a[1] * alpha;
                float2 hi; hi.x = a[2] * alpha; hi.y = a[3] * alpha;
                *(float2*)(C + r0 * (long)ldc + col) = lo;
                *(float2*)(C + (r0 + 8) * (long)ldc + col) = hi;
            }
        }
    } else {
        __half* C = (__half*)Cv + (long)blockIdx.z * sC;
        #pragma unroll
        for (int mi = 0; mi < 4; ++mi) {
            long r0 = m0 + mw + mi * 16 + g;
            #pragma unroll
            for (int ni = 0; ni < 8; ++ni) {
                long col = n0 + nw + ni * 8 + 2 * tig;
                const float* a = acc[mi * 8 + ni];
                *(__half2*)(C + r0 * (long)ldc + col) =
                    __floats2half2_rn(a[0] * alpha, a[1] * alpha);
                *(__half2*)(C + (r0 + 8) * (long)ldc + col) =
                    __floats2half2_rn(a[2] * alpha, a[3] * alpha);
            }
        }
    }
}

// ---------------------------------------------------------------------------
// Fused prep: blocks [0,2048): f2h of x; [2048,2048+3072): wconv; last: packb.
// All parts use 256 threads.
// ---------------------------------------------------------------------------
__global__ __launch_bounds__(256) void prep(
    const float* __restrict__ x, __half* __restrict__ Xh,
    const float* __restrict__ Wq, const float* __restrict__ Wk,
    const float* __restrict__ Wv, __half* __restrict__ W3,
    const float* __restrict__ bq, const float* __restrict__ bk,
    const float* __restrict__ bv, float* __restrict__ b3)
{
    const int bid = blockIdx.x;
    const int t = threadIdx.x;
    if (bid < 2048) {
        // f2h: 16M floats, grid-stride over 2048 blocks
        const long n = (long)BATCH * SEQ * DIM;
        for (long i = ((long)bid * 256 + t) * 4; i < n; i += 2048L * 256 * 4) {
            float4 v = *reinterpret_cast<const float4*>(x + i);
            *(__half2*)(Xh + i)     = __floats2half2_rn(v.x, v.y);
            *(__half2*)(Xh + i + 2) = __floats2half2_rn(v.z, v.w);
        }
    } else if (bid < 2048 + 3072) {
        // wconv: transpose+convert one 32x32 tile
        __shared__ float tbuf[32][33];
        const int r = bid - 2048;
        const int zz = r >> 10;            // 0..2 (which W)
        const int rem = r & 1023;
        const int by = rem >> 5, bx = rem & 31;
        const float* W = zz == 0 ? Wq : (zz == 1 ? Wk : Wv);
        const int d0 = by * 32, h0 = bx * 32;
        const int tx = t & 31, ty = t >> 5;
        #pragma unroll
        for (int i = 0; i < 32; i += 8)
            tbuf[ty + i][tx] = W[(long)(d0 + ty + i) * DIM + h0 + tx];
        __syncthreads();
        #pragma unroll
        for (int i = 0; i < 32; i += 8)
            W3[((size_t)zz * DIM + h0 + ty + i) * DIM + d0 + tx] =
                __float2half_rn(tbuf[tx][ty + i]);
    } else {
        // packb: 3072 floats over 12 blocks
        int i = (bid - 2048 - 3072) * 256 + t;
        if (i < H3)
            b3[i] = i < DIM ? bq[i] : (i < 2 * DIM ? bk[i - DIM] : bv[i - 2 * DIM]);
    }
}

// ---------------------------------------------------------------------------
// fp16 transpose per batch: out[c][r] = in[r][c]; in ld = ldin, out ld = rows
// ---------------------------------------------------------------------------
__global__ void transpose_h(const __half* __restrict__ in, __half* __restrict__ out,
                            int rows, int ldin, long sIn, long sOut)
{
    __shared__ __half t[32][33];
    in += (long)blockIdx.z * sIn;
    out += (long)blockIdx.z * sOut;
    const int r0 = blockIdx.y * 32, c0 = blockIdx.x * 32;
    const int tx = threadIdx.x, ty = threadIdx.y;
    #pragma unroll
    for (int i = 0; i < 32; i += 8)
        t[ty + i][tx] = in[(long)(r0 + ty + i) * ldin + c0 + tx];
    __syncthreads();
    #pragma unroll
    for (int i = 0; i < 32; i += 8)
        out[(long)(c0 + ty + i) * rows + r0 + tx] = t[tx][ty + i];
}

// ---------------------------------------------------------------------------
// Row softmax over SEQ=2048: S (fp16) -> P (fp16). Warp-shuffle reductions.
// ---------------------------------------------------------------------------
__global__ __launch_bounds__(256) void softmax_rows(const __half* __restrict__ S,
                                                    __half* __restrict__ P)
{
    const __half* p = S + (long)blockIdx.x * SEQ;
    __half* q = P + (long)blockIdx.x * SEQ;
    const int tid = threadIdx.x;
    const int wid = tid >> 5, lane = tid & 31;
    __shared__ float red[8];

    uint2 w0 = *(const uint2*)(p + tid * 4);
    uint2 w1 = *(const uint2*)(p + 1024 + tid * 4);
    float2 a0 = __half22float2(*(__half2*)&w0.x);
    float2 a1 = __half22float2(*(__half2*)&w0.y);
    float2 a2 = __half22float2(*(__half2*)&w1.x);
    float2 a3 = __half22float2(*(__half2*)&w1.y);
    float4 v0; v0.x = a0.x; v0.y = a0.y; v0.z = a1.x; v0.w = a1.y;
    float4 v1; v1.x = a2.x; v1.y = a2.y; v1.z = a3.x; v1.w = a3.y;

    float m = fmaxf(fmaxf(fmaxf(v0.x, v0.y), fmaxf(v0.z, v0.w)),
                    fmaxf(fmaxf(v1.x, v1.y), fmaxf(v1.z, v1.w)));
    #pragma unroll
    for (int s = 16; s > 0; s >>= 1)
        m = fmaxf(m, __shfl_xor_sync(0xFFFFFFFFu, m, s));
    if (lane == 0) red[wid] = m;
    __syncthreads();
    float m0 = red[0];
    #pragma unroll
    for (int w = 1; w < 8; ++w) m0 = fmaxf(m0, red[w]);
    __syncthreads();

    v0.x = __expf(v0.x - m0); v0.y = __expf(v0.y - m0);
    v0.z = __expf(v0.z - m0); v0.w = __expf(v0.w - m0);
    v1.x = __expf(v1.x - m0); v1.y = __expf(v1.y - m0);
    v1.z = __expf(v1.z - m0); v1.w = __expf(v1.w - m0);

    float sum = (v0.x + v0.y) + (v0.z + v0.w) + (v1.x + v1.y) + (v1.z + v1.w);
    #pragma unroll
    for (int s = 16; s > 0; s >>= 1)
        sum += __shfl_xor_sync(0xFFFFFFFFu, sum, s);
    if (lane == 0) red[wid] = sum;
    __syncthreads();
    float tot = red[0];
    #pragma unroll
    for (int w = 1; w < 8; ++w) tot += red[w];
    const float inv = 1.f / tot;

    *(__half2*)(q + tid * 4)     = __floats2half2_rn(v0.x * inv, v0.y * inv);
    *(__half2*)(q + tid * 4 + 2) = __floats2half2_rn(v0.z * inv, v0.w * inv);
    *(__half2*)(q + 1024 + tid * 4)     = __floats2half2_rn(v1.x * inv, v1.y * inv);
    *(__half2*)(q + 1024 + tid * 4 + 2) = __floats2half2_rn(v1.z * inv, v1.w * inv);
}

// ---------------------------------------------------------------------------
extern "C" void kernel_launch(void* const* d_in, const int* in_sizes, int n_in,
                              void* d_out, int out_size)
{
    const float* x  = (const float*)d_in[0];
    const float* Wq = (const float*)d_in[1];
    const float* bq = (const float*)d_in[2];
    const float* Wk = (const float*)d_in[3];
    const float* bk = (const float*)d_in[4];
    const float* Wv = (const float*)d_in[5];
    const float* bv = (const float*)d_in[6];
    float* out = (float*)d_out;

    __half *Xh, *W3, *QKV, *Vt, *S, *P;
    float *b3;
    cudaGetSymbolAddress((void**)&Xh,  g_Xh);
    cudaGetSymbolAddress((void**)&W3,  g_W3);
    cudaGetSymbolAddress((void**)&b3,  g_b3);
    cudaGetSymbolAddress((void**)&QKV, g_QKV);
    cudaGetSymbolAddress((void**)&Vt,  g_Vt);
    cudaGetSymbolAddress((void**)&S,   g_S);
    cudaGetSymbolAddress((void**)&P,   g_P);

    cudaFuncSetAttribute(hgemm<0>, cudaFuncAttributeMaxDynamicSharedMemorySize, SMEM_BYTES);
    cudaFuncSetAttribute(hgemm<1>, cudaFuncAttributeMaxDynamicSharedMemorySize, SMEM_BYTES);
    cudaFuncSetAttribute(hgemm<2>, cudaFuncAttributeMaxDynamicSharedMemorySize, SMEM_BYTES);

    const long SD = (long)SEQ * DIM;
    const long SS = (long)SEQ * SEQ;
    const long SH3 = (long)SEQ * H3;
    dim3 tb(32, 8);

    // fused input conversions (f2h + wconv + packb)
    prep<<<2048 + 3072 + 12, 256>>>(x, Xh, Wq, Wk, Wv, W3, bq, bk, bv, b3);

    // fused QKV projection: [16384,1024] x [3072,1024]^T + bias -> half [s][3H]
    hgemm<0><<<dim3(H3 / 128, (BATCH * SEQ) / 128, 1), 128, SMEM_BYTES>>>(
        Xh, W3, b3, QKV, DIM, DIM, H3, DIM / 32, 0, 0, 0, 1.f);

    // scores = Q K^T / 32 -> fp16 S
    hgemm<2><<<dim3(SEQ / 128, SEQ / 128, BATCH), 128, SMEM_BYTES>>>(
        QKV, QKV + DIM, nullptr, S, H3, H3, SEQ, DIM / 32,
        SH3, SH3, SS, 1.f / 32.f);

    // softmax -> fp16 probs
    softmax_rows<<<BATCH * SEQ, 256>>>(S, P);

    // V^T per batch: [S,3H slice] -> [H,S]
    transpose_h<<<dim3(DIM / 32, SEQ / 32, BATCH), tb>>>(
        QKV + 2 * DIM, Vt, SEQ, H3, SH3, SD);

    // out = P V (fp32 out)
    hgemm<1><<<dim3(DIM / 128, SEQ / 128, BATCH), 128, SMEM_BYTES>>>(
        P, Vt, nullptr, out, SEQ, SEQ, DIM, SEQ / 32,
        SS, SD, SD, 1.f);
}

// round 17
// speedup vs baseline: 1.0770x; 1.0616x over previous
#include <cuda_runtime.h>
#include <cuda_fp16.h>
#include <cstdint>
#include <math.h>

#define BATCH 8
#define SEQ   2048
#define DIM   1024
#define H3    3072

// Scratch (__device__ globals; no allocs allowed)
__device__ __half g_Xh [(size_t)BATCH * SEQ * DIM];   // x in fp16
__device__ __half g_W3 [(size_t)H3 * DIM];            // [Wq;Wk;Wv]^T packed, K-major [3H][D]
__device__ float  g_b3 [H3];                          // packed bias
__device__ __half g_QKV[(size_t)BATCH * SEQ * H3];    // [s][3H] fp16
__device__ __half g_S  [(size_t)BATCH * SEQ * SEQ];   // scores fp16
__device__ __half g_P  [(size_t)BATCH * SEQ * SEQ];   // softmax probs fp16

// ------------------------------ helpers ------------------------------
__device__ __forceinline__ uint32_t smem_u32(const void* p) {
    uint32_t a;
    asm("{ .reg .u64 t; cvta.to.shared.u64 t, %1; cvt.u32.u64 %0, t; }"
        : "=r"(a) : "l"(p));
    return a;
}

#define LDSM_X4(r, addr) \
    asm volatile("ldmatrix.sync.aligned.m8n8.x4.shared.b16 {%0,%1,%2,%3}, [%4];" \
        : "=r"((r)[0]), "=r"((r)[1]), "=r"((r)[2]), "=r"((r)[3]) : "r"(addr))

#define LDSM_X4_T(r, addr) \
    asm volatile("ldmatrix.sync.aligned.m8n8.x4.trans.shared.b16 {%0,%1,%2,%3}, [%4];" \
        : "=r"((r)[0]), "=r"((r)[1]), "=r"((r)[2]), "=r"((r)[3]) : "r"(addr))

#define MMA16816(c, a, b0_, b1_) \
    asm volatile("mma.sync.aligned.m16n8k16.row.col.f32.f16.f16.f32 " \
        "{%0,%1,%2,%3}, {%4,%5,%6,%7}, {%8,%9}, {%0,%1,%2,%3};" \
        : "+f"((c)[0]), "+f"((c)[1]), "+f"((c)[2]), "+f"((c)[3]) \
        : "r"((a)[0]), "r"((a)[1]), "r"((a)[2]), "r"((a)[3]), \
          "r"(b0_), "r"(b1_))

#define CP_ASYNC16(dst, src) \
    asm volatile("cp.async.cg.shared.global [%0], [%1], 16;" :: "r"(dst), "l"(src))

#define NST     4
#define ROWPAD  80                        // 32 halves (64B) padded to 80B
#define BPITCH  272                       // TRANSB: 128 halves (256B) padded to 272B
#define ASTAGE  (128 * ROWPAD)            // 10240B
#define STAGE   (2 * ASTAGE)              // A + B = 20480B (TRANSB B: 32*272=8704 fits)
#define SMEM_BYTES (NST * STAGE)          // 81920B

// ---------------------------------------------------------------------------
// fp16 tensor-core GEMM: C[m0:+128, n0:+128] = A * op(B)  (A K-major)
// TRANSB=0: B [N,K] row-major (ld=ldb), normal ldmatrix.
// TRANSB=1: B [K,N] row-major (ld=ldb), trans ldmatrix (B tile 32k x 128n).
// MODE 0: C half, += bias (fp32), no batch (QKV).
// MODE 1: C float, *= alpha, batched (PV -> final out).
// MODE 2: C half,  *= alpha, batched (scores -> fp16 S).
// 128 threads, 4 warps in 2x2; warp tile 64x64 (32 indep MMAs per k16).
// R9 structure: NST=4, BK=32, interleaved LDSM/MMA, 2 CTAs/SM.
// ---------------------------------------------------------------------------
template <int MODE, int TRANSB>
__global__ __launch_bounds__(128, 2) void hgemm(
    const __half* __restrict__ Ag, const __half* __restrict__ Bg,
    const float* __restrict__ bias, void* __restrict__ Cv,
    int lda, int ldb, int ldc, int kIters,
    long sA, long sB, long sC, float alpha)
{
    extern __shared__ char dsm[];
    const uint32_t sm0 = smem_u32(dsm);
    const int tid = threadIdx.x;
    const int wid = tid >> 5, lane = tid & 31;
    const __half* A = Ag + (long)blockIdx.z * sA;
    const __half* B = Bg + (long)blockIdx.z * sB;
    const long m0 = (long)blockIdx.y * 128;
    const long n0 = (long)blockIdx.x * 128;
    const int mw = (wid >> 1) * 64;   // warp row offset in tile
    const int nw = (wid & 1) * 64;    // warp col offset in tile

    const int g = lane >> 2, tig = lane & 3;
    // normal ldmatrix per-lane offsets (bytes), conflict-free with ROWPAD=80
    const uint32_t aOff = ((lane & 7) + ((lane >> 3) & 1) * 8) * ROWPAD
                        + ((lane >> 4) & 1) * 16;
    const uint32_t bOff = ((lane & 7) + ((lane >> 4) & 1) * 8) * ROWPAD
                        + ((lane >> 3) & 1) * 16;
    // trans ldmatrix per-lane offsets over [k][n] tile, pitch 272B:
    // lanes 0-15 -> k-rows 0-15 @h+0 (m0,m1); lanes 16-31 -> k-rows 0-15 @h+8 (m2,m3)
    const uint32_t bOffT = (lane & 15) * BPITCH + ((lane >> 4) & 1) * 16;

    auto load_stage = [&](int s, int it) {
        const uint32_t ab = sm0 + s * STAGE;
        const long kb = (long)it * 32;
        #pragma unroll
        for (int i = 0; i < 4; ++i) {                 // A: 128 rows x 64B
            int idx = tid + i * 128;
            int row = idx >> 2, c = idx & 3;
            const __half* src = A + (m0 + row) * (long)lda + kb + c * 8;
            CP_ASYNC16(ab + row * ROWPAD + c * 16, src);
        }
        if (TRANSB) {
            #pragma unroll
            for (int i = 0; i < 4; ++i) {             // B: 32 k-rows x 256B
                int idx = tid + i * 128;
                int row = idx >> 4, c = idx & 15;
                const __half* src = B + (kb + row) * (long)ldb + n0 + c * 8;
                CP_ASYNC16(ab + ASTAGE + row * BPITCH + c * 16, src);
            }
        } else {
            #pragma unroll
            for (int i = 0; i < 4; ++i) {             // B: 128 n-rows x 64B
                int idx = tid + i * 128;
                int row = idx >> 2, c = idx & 3;
                const __half* src = B + (n0 + row) * (long)ldb + kb + c * 8;
                CP_ASYNC16(ab + ASTAGE + row * ROWPAD + c * 16, src);
            }
        }
    };

    float acc[32][4];
    #pragma unroll
    for (int t = 0; t < 32; ++t)
        acc[t][0] = acc[t][1] = acc[t][2] = acc[t][3] = 0.f;

    #pragma unroll
    for (int s = 0; s < NST - 1; ++s) {
        load_stage(s, s);
        asm volatile("cp.async.commit_group;" ::: "memory");
    }

    for (int it = 0; it < kIters; ++it) {
        asm volatile("cp.async.wait_group 2;" ::: "memory");
        __syncthreads();

        {   // prefetch next stage (writes stage computed 3 iters ago — safe)
            int nit = it + NST - 1;
            if (nit < kIters) load_stage(nit & (NST - 1), nit);
            asm volatile("cp.async.commit_group;" ::: "memory");
        }

        const uint32_t ab = sm0 + (it & (NST - 1)) * STAGE;
        const uint32_t bb = ab + ASTAGE;
        const uint32_t aBase = ab + mw * ROWPAD + aOff;
        const uint32_t bBase = TRANSB ? (bb + nw * 2 + bOffT)
                                      : (bb + nw * ROWPAD + bOff);

        uint32_t af0[4][4], bf0[4][4], af1[4][4], bf1[4][4];

        // kk=0 fragment loads
        #pragma unroll
        for (int mi = 0; mi < 4; ++mi)
            LDSM_X4(af0[mi], aBase + mi * (16 * ROWPAD));
        #pragma unroll
        for (int nj = 0; nj < 4; ++nj) {
            if (TRANSB) LDSM_X4_T(bf0[nj], bBase + nj * 32);
            else        LDSM_X4(bf0[nj], bBase + nj * (16 * ROWPAD));
        }

        // kk=0 MMAs, first half (mi 0..1)
        #pragma unroll
        for (int mi = 0; mi < 2; ++mi)
            #pragma unroll
            for (int ni = 0; ni < 8; ++ni)
                MMA16816(acc[mi * 8 + ni], af0[mi],
                         bf0[ni >> 1][(ni & 1) * 2],
                         bf0[ni >> 1][(ni & 1) * 2 + 1]);

        // kk=1 A fragments — hidden under kk0 MMA stream
        #pragma unroll
        for (int mi = 0; mi < 4; ++mi)
            LDSM_X4(af1[mi], aBase + mi * (16 * ROWPAD) + 32);

        // kk=0 MMAs, second half (mi 2..3); af0 dies here
        #pragma unroll
        for (int mi = 2; mi < 4; ++mi)
            #pragma unroll
            for (int ni = 0; ni < 8; ++ni)
                MMA16816(acc[mi * 8 + ni], af0[mi],
                         bf0[ni >> 1][(ni & 1) * 2],
                         bf0[ni >> 1][(ni & 1) * 2 + 1]);

        // kk=1 B fragments
        #pragma unroll
        for (int nj = 0; nj < 4; ++nj) {
            if (TRANSB) LDSM_X4_T(bf1[nj], bBase + nj * 32 + 16 * BPITCH);
            else        LDSM_X4(bf1[nj], bBase + nj * (16 * ROWPAD) + 32);
        }

        // kk=1 MMAs
        #pragma unroll
        for (int mi = 0; mi < 4; ++mi)
            #pragma unroll
            for (int ni = 0; ni < 8; ++ni)
                MMA16816(acc[mi * 8 + ni], af1[mi],
                         bf1[ni >> 1][(ni & 1) * 2],
                         bf1[ni >> 1][(ni & 1) * 2 + 1]);
    }

    // ---- epilogue: warp writes its 64x64 tile ----
    if (MODE == 0) {
        __half* C = (__half*)Cv;
        #pragma unroll
        for (int mi = 0; mi < 4; ++mi) {
            long r0 = m0 + mw + mi * 16 + g;
            #pragma unroll
            for (int ni = 0; ni < 8; ++ni) {
                long col = n0 + nw + ni * 8 + 2 * tig;
                float bx = __ldg(&bias[col]), by = __ldg(&bias[col + 1]);
                const float* a = acc[mi * 8 + ni];
                *(__half2*)(C + r0 * (long)ldc + col) =
                    __floats2half2_rn(a[0] + bx, a[1] + by);
                *(__half2*)(C + (r0 + 8) * (long)ldc + col) =
                    __floats2half2_rn(a[2] + bx, a[3] + by);
            }
        }
    } else if (MODE == 1) {
        float* C = (float*)Cv + (long)blockIdx.z * sC;
        #pragma unroll
        for (int mi = 0; mi < 4; ++mi) {
            long r0 = m0 + mw + mi * 16 + g;
            #pragma unroll
            for (int ni = 0; ni < 8; ++ni) {
                long col = n0 + nw + ni * 8 + 2 * tig;
                const float* a = acc[mi * 8 + ni];
                float2 lo; lo.x = a[0] * alpha; lo.y = a[1] * alpha;
                float2 hi; hi.x = a[2] * alpha; hi.y = a[3] * alpha;
                *(float2*)(C + r0 * (long)ldc + col) = lo;
                *(float2*)(C + (r0 + 8) * (long)ldc + col) = hi;
            }
        }
    } else {
        __half* C = (__half*)Cv + (long)blockIdx.z * sC;
        #pragma unroll
        for (int mi = 0; mi < 4; ++mi) {
            long r0 = m0 + mw + mi * 16 + g;
            #pragma unroll
            for (int ni = 0; ni < 8; ++ni) {
                long col = n0 + nw + ni * 8 + 2 * tig;
                const float* a = acc[mi * 8 + ni];
                *(__half2*)(C + r0 * (long)ldc + col) =
                    __floats2half2_rn(a[0] * alpha, a[1] * alpha);
                *(__half2*)(C + (r0 + 8) * (long)ldc + col) =
                    __floats2half2_rn(a[2] * alpha, a[3] * alpha);
            }
        }
    }
}

// ---------------------------------------------------------------------------
// Fused prep: blocks [0,2048): f2h of x; [2048,2048+3072): wconv; last: packb.
// ---------------------------------------------------------------------------
__global__ __launch_bounds__(256) void prep(
    const float* __restrict__ x, __half* __restrict__ Xh,
    const float* __restrict__ Wq, const float* __restrict__ Wk,
    const float* __restrict__ Wv, __half* __restrict__ W3,
    const float* __restrict__ bq, const float* __restrict__ bk,
    const float* __restrict__ bv, float* __restrict__ b3)
{
    const int bid = blockIdx.x;
    const int t = threadIdx.x;
    if (bid < 2048) {
        const long n = (long)BATCH * SEQ * DIM;
        for (long i = ((long)bid * 256 + t) * 4; i < n; i += 2048L * 256 * 4) {
            float4 v = *reinterpret_cast<const float4*>(x + i);
            *(__half2*)(Xh + i)     = __floats2half2_rn(v.x, v.y);
            *(__half2*)(Xh + i + 2) = __floats2half2_rn(v.z, v.w);
        }
    } else if (bid < 2048 + 3072) {
        __shared__ float tbuf[32][33];
        const int r = bid - 2048;
        const int zz = r >> 10;
        const int rem = r & 1023;
        const int by = rem >> 5, bx = rem & 31;
        const float* W = zz == 0 ? Wq : (zz == 1 ? Wk : Wv);
        const int d0 = by * 32, h0 = bx * 32;
        const int tx = t & 31, ty = t >> 5;
        #pragma unroll
        for (int i = 0; i < 32; i += 8)
            tbuf[ty + i][tx] = W[(long)(d0 + ty + i) * DIM + h0 + tx];
        __syncthreads();
        #pragma unroll
        for (int i = 0; i < 32; i += 8)
            W3[((size_t)zz * DIM + h0 + ty + i) * DIM + d0 + tx] =
                __float2half_rn(tbuf[tx][ty + i]);
    } else {
        int i = (bid - 2048 - 3072) * 256 + t;
        if (i < H3)
            b3[i] = i < DIM ? bq[i] : (i < 2 * DIM ? bk[i - DIM] : bv[i - 2 * DIM]);
    }
}

// ---------------------------------------------------------------------------
// Row softmax over SEQ=2048: S (fp16) -> P (fp16). Warp-shuffle reductions.
// ---------------------------------------------------------------------------
__global__ __launch_bounds__(256) void softmax_rows(const __half* __restrict__ S,
                                                    __half* __restrict__ P)
{
    const __half* p = S + (long)blockIdx.x * SEQ;
    __half* q = P + (long)blockIdx.x * SEQ;
    const int tid = threadIdx.x;
    const int wid = tid >> 5, lane = tid & 31;
    __shared__ float red[8];

    uint2 w0 = *(const uint2*)(p + tid * 4);
    uint2 w1 = *(const uint2*)(p + 1024 + tid * 4);
    float2 a0 = __half22float2(*(__half2*)&w0.x);
    float2 a1 = __half22float2(*(__half2*)&w0.y);
    float2 a2 = __half22float2(*(__half2*)&w1.x);
    float2 a3 = __half22float2(*(__half2*)&w1.y);
    float4 v0; v0.x = a0.x; v0.y = a0.y; v0.z = a1.x; v0.w = a1.y;
    float4 v1; v1.x = a2.x; v1.y = a2.y; v1.z = a3.x; v1.w = a3.y;

    float m = fmaxf(fmaxf(fmaxf(v0.x, v0.y), fmaxf(v0.z, v0.w)),
                    fmaxf(fmaxf(v1.x, v1.y), fmaxf(v1.z, v1.w)));
    #pragma unroll
    for (int s = 16; s > 0; s >>= 1)
        m = fmaxf(m, __shfl_xor_sync(0xFFFFFFFFu, m, s));
    if (lane == 0) red[wid] = m;
    __syncthreads();
    float m0 = red[0];
    #pragma unroll
    for (int w = 1; w < 8; ++w) m0 = fmaxf(m0, red[w]);
    __syncthreads();

    v0.x = __expf(v0.x - m0); v0.y = __expf(v0.y - m0);
    v0.z = __expf(v0.z - m0); v0.w = __expf(v0.w - m0);
    v1.x = __expf(v1.x - m0); v1.y = __expf(v1.y - m0);
    v1.z = __expf(v1.z - m0); v1.w = __expf(v1.w - m0);

    float sum = (v0.x + v0.y) + (v0.z + v0.w) + (v1.x + v1.y) + (v1.z + v1.w);
    #pragma unroll
    for (int s = 16; s > 0; s >>= 1)
        sum += __shfl_xor_sync(0xFFFFFFFFu, sum, s);
    if (lane == 0) red[wid] = sum;
    __syncthreads();
    float tot = red[0];
    #pragma unroll
    for (int w = 1; w < 8; ++w) tot += red[w];
    const float inv = 1.f / tot;

    *(__half2*)(q + tid * 4)     = __floats2half2_rn(v0.x * inv, v0.y * inv);
    *(__half2*)(q + tid * 4 + 2) = __floats2half2_rn(v0.z * inv, v0.w * inv);
    *(__half2*)(q + 1024 + tid * 4)     = __floats2half2_rn(v1.x * inv, v1.y * inv);
    *(__half2*)(q + 1024 + tid * 4 + 2) = __floats2half2_rn(v1.z * inv, v1.w * inv);
}

// ---------------------------------------------------------------------------
extern "C" void kernel_launch(void* const* d_in, const int* in_sizes, int n_in,
                              void* d_out, int out_size)
{
    const float* x  = (const float*)d_in[0];
    const float* Wq = (const float*)d_in[1];
    const float* bq = (const float*)d_in[2];
    const float* Wk = (const float*)d_in[3];
    const float* bk = (const float*)d_in[4];
    const float* Wv = (const float*)d_in[5];
    const float* bv = (const float*)d_in[6];
    float* out = (float*)d_out;

    __half *Xh, *W3, *QKV, *S, *P;
    float *b3;
    cudaGetSymbolAddress((void**)&Xh,  g_Xh);
    cudaGetSymbolAddress((void**)&W3,  g_W3);
    cudaGetSymbolAddress((void**)&b3,  g_b3);
    cudaGetSymbolAddress((void**)&QKV, g_QKV);
    cudaGetSymbolAddress((void**)&S,   g_S);
    cudaGetSymbolAddress((void**)&P,   g_P);

    cudaFuncSetAttribute((const void*)hgemm<0,0>, cudaFuncAttributeMaxDynamicSharedMemorySize, SMEM_BYTES);
    cudaFuncSetAttribute((const void*)hgemm<2,0>, cudaFuncAttributeMaxDynamicSharedMemorySize, SMEM_BYTES);
    cudaFuncSetAttribute((const void*)hgemm<1,1>, cudaFuncAttributeMaxDynamicSharedMemorySize, SMEM_BYTES);

    const long SD = (long)SEQ * DIM;
    const long SS = (long)SEQ * SEQ;
    const long SH3 = (long)SEQ * H3;

    // fused input conversions (f2h + wconv + packb)
    prep<<<2048 + 3072 + 12, 256>>>(x, Xh, Wq, Wk, Wv, W3, bq, bk, bv, b3);

    // fused QKV projection: [16384,1024] x [3072,1024]^T + bias -> half [s][3H]
    hgemm<0,0><<<dim3(H3 / 128, (BATCH * SEQ) / 128, 1), 128, SMEM_BYTES>>>(
        Xh, W3, b3, QKV, DIM, DIM, H3, DIM / 32, 0, 0, 0, 1.f);

    // scores = Q K^T / 32 -> fp16 S
    hgemm<2,0><<<dim3(SEQ / 128, SEQ / 128, BATCH), 128, SMEM_BYTES>>>(
        QKV, QKV + DIM, nullptr, S, H3, H3, SEQ, DIM / 32,
        SH3, SH3, SS, 1.f / 32.f);

    // softmax -> fp16 probs
    softmax_rows<<<BATCH * SEQ, 256>>>(S, P);

    // out = P V (fp32 out); V read straight from QKV via trans-ldmatrix
    hgemm<1,1><<<dim3(DIM / 128, SEQ / 128, BATCH), 128, SMEM_BYTES>>>(
        P, QKV + 2 * DIM, nullptr, out, SEQ, H3, DIM, SEQ / 32,
        SS, SH3, SD, 1.f);
}